// round 5
// baseline (speedup 1.0000x reference)
#include <cuda_runtime.h>
#include <cstddef>

// DCTFeatureModel — collapsed linear model, SINGLE fused kernel:
//   phase A (all 512 CTAs): compute a (s,o,t-quarter) slice of
//       Veff[s,o,t,i,j] = (1/8) sum_{f,p,q} Ct[f,t] Cs[p,i] Cs[q,j] W[s,o,f,p,q]
//   device-wide barrier (atomic counter + acquire spin; all CTAs resident)
//   phase B: k-split GEMM  feat_part[ks][b][s,o] = sum xc * Veff
//   phase C: last CTA per (s,mt) group reduces 16 partials + bias + LeakyReLU.

#define NSW 2
#define NF 64
#define KSPLIT 16
#define MTILES 16
#define GRID 512

__device__ __align__(16) float g_veff[NSW * 32 * 64 * 64];        // [s][t][ij][o], 1 MB
__device__ __align__(16) float g_part[KSPLIT * 1024 * NSW * NF];  // 8 MB
__device__ int g_prep_ctr;   // 0 at every launch start (reset at end of launch)
__device__ int g_grp[32];    // per-(s,mt) arrival counters (reset by each winner)
__device__ int g_done;       // reducer count (reset by last)

typedef unsigned long long u64;

__device__ __forceinline__ u64 pk2(float a, float b) {
    u64 r; asm("mov.b64 %0,{%1,%2};" : "=l"(r) : "f"(a), "f"(b)); return r;
}
__device__ __forceinline__ float2 up2(u64 a) {
    float2 v; asm("mov.b64 {%0,%1},%2;" : "=f"(v.x), "=f"(v.y) : "l"(a)); return v;
}
__device__ __forceinline__ void fma2(u64& d, u64 a, u64 b) {
    asm("fma.rn.f32x2 %0,%1,%2,%0;" : "+l"(d) : "l"(a), "l"(b));
}
__device__ __forceinline__ u64 add2(u64 a, u64 b) {
    u64 r; asm("add.rn.f32x2 %0,%1,%2;" : "=l"(r) : "l"(a), "l"(b)); return r;
}

// shared pool layout (floats):
//   GEMM:  xs[2][32][68] = pool[0..4352)   ws[2][32][64] = pool[4352..8448)
//   prep:  A[2048]=pool[0..2048) Bf[512]=pool[2048..2560) B2[512]=pool[2560..3072)
//          Ct[256]=pool[3072..3328) Cs[64]=pool[3328..3392) Cst[64]=pool[3392..3456)
#define XS(buf, ij, b) pool[(buf) * 2176 + (ij) * 68 + (b)]
#define WSBASE(buf) (pool + 4352 + (buf) * 2048)

__global__ void __launch_bounds__(256, 4) fused_kernel(
    const float* __restrict__ x, const float* __restrict__ W,
    const float* __restrict__ bias, float* __restrict__ out) {
    __shared__ __align__(16) float pool[8448];
    __shared__ int s_win;

    const int tid = threadIdx.x;
    const int bx = blockIdx.x;

    // ======================= phase A: prep (quartered) =======================
    {
        const int tq = bx & 3;
        const int op = (bx >> 2) & 63;
        const int sp = bx >> 8;
        float* A = pool;
        float* Bf = pool + 2048;
        float* B2 = pool + 2560;
        float* Ct = pool + 3072;
        float* Cs = pool + 3328;
        float* Cst = pool + 3392;

        {   // tables
            int tl = tid >> 5, f = tid & 31;
            Ct[tid] = 2.0f * cospif((float)((2 * (tq * 8 + tl) + 1) * f) / 64.0f);
            if (tid < 64) {
                int i = tid >> 3, p = tid & 7;
                Cs[tid] = 2.0f * cospif((float)((2 * i + 1) * p) / 16.0f);
            } else if (tid < 128) {
                int e = tid - 64, q = e >> 3, j = e & 7;
                Cst[e] = 2.0f * cospif((float)((2 * j + 1) * q) / 16.0f);
            }
        }
        {   // W(s,o) -> A
            const float4* Wso = (const float4*)(W + ((size_t)(sp * 64 + op) << 11));
            ((float4*)A)[tid] = Wso[tid];
            ((float4*)A)[tid + 256] = Wso[tid + 256];
        }
        __syncthreads();

        if (tid < 128) {  // stage 1: f -> t (our 8 t's)
            int tl = tid >> 4, g = tid & 15;
            u64 a01 = 0, a23 = 0;
#pragma unroll
            for (int f = 0; f < 32; ++f) {
                float4 av = ((const float4*)A)[f * 16 + g];
                float c = Ct[tl * 32 + f];
                u64 cc = pk2(c, c);
                fma2(a01, pk2(av.x, av.y), cc);
                fma2(a23, pk2(av.z, av.w), cc);
            }
            float2 v0 = up2(a01), v1 = up2(a23);
            *(float4*)&Bf[tl * 64 + 4 * g] = make_float4(v0.x, v0.y, v1.x, v1.y);
        }
        __syncthreads();

        if (tid < 128) {  // stage 2: p -> i
            int tl = tid >> 4, i = (tid >> 1) & 7, qg = tid & 1;
            u64 a01 = 0, a23 = 0;
#pragma unroll
            for (int p = 0; p < 8; ++p) {
                float4 bv = *(const float4*)&Bf[tl * 64 + p * 8 + 4 * qg];
                float c = Cs[i * 8 + p];
                u64 cc = pk2(c, c);
                fma2(a01, pk2(bv.x, bv.y), cc);
                fma2(a23, pk2(bv.z, bv.w), cc);
            }
            float2 v0 = up2(a01), v1 = up2(a23);
            *(float4*)&B2[tl * 64 + i * 8 + 4 * qg] = make_float4(v0.x, v0.y, v1.x, v1.y);
        }
        __syncthreads();

        if (tid < 128) {  // stage 3: q -> j, scale, scatter to g_veff
            int tl = tid >> 4, i = (tid >> 1) & 7, jg = tid & 1;
            float4 ba = *(const float4*)&B2[tl * 64 + i * 8];
            float4 bb = *(const float4*)&B2[tl * 64 + i * 8 + 4];
            float bq[8] = {ba.x, ba.y, ba.z, ba.w, bb.x, bb.y, bb.z, bb.w};
            u64 a01 = 0, a23 = 0;
#pragma unroll
            for (int q = 0; q < 8; ++q) {
                float4 cj = *(const float4*)&Cst[q * 8 + 4 * jg];
                u64 bp = pk2(bq[q], bq[q]);
                fma2(a01, bp, pk2(cj.x, cj.y));
                fma2(a23, bp, pk2(cj.z, cj.w));
            }
            int t = tq * 8 + tl;
            float* base = g_veff + (((size_t)(sp * 32 + t) << 6) + i * 8 + 4 * jg) * 64 + op;
            float2 v0 = up2(a01), v1 = up2(a23);
            base[0] = 0.125f * v0.x;
            base[64] = 0.125f * v0.y;
            base[128] = 0.125f * v1.x;
            base[192] = 0.125f * v1.y;
        }
        __threadfence();
        __syncthreads();
        if (tid == 0) atomicAdd(&g_prep_ctr, 1);
    }

    // ======================= phase B: GEMM =======================
    const int ks = bx & 15;
    const int mt = (bx >> 4) & 15;
    const int sg = bx >> 8;

    const int ijp = tid & 15, bb = tid >> 4;  // load map
    const int tx = tid & 15, ty = tid >> 4;   // compute map

    const float* xb = x + (size_t)(mt * 64 + bb * 4) * 32768 + (size_t)sg * 16384 + 2 * ijp;

    u64 acc[2][4] = {};
    u64 xr[8];
    float4 wr0, wr1;

#define PH_T(ph) (ks * 2 + ((ph) >> 1))
#define PH_OFF(ph) ((size_t)(PH_T(ph)) * 64 + ((ph) & 1) * 32)

#define LDG_U(ph, u)                                                          \
    do {                                                                      \
        const u64* p = (const u64*)(xb + (size_t)(u) * 32768 + PH_OFF(ph));   \
        _Pragma("unroll") for (int c = 0; c < 8; ++c) xr[c] = p[c * 1024];    \
    } while (0)

#define STS_U(buf, u)                                                         \
    do {                                                                      \
        u64 s0 = add2(add2(xr[0], xr[1]), add2(xr[2], xr[3]));                \
        u64 s1 = add2(add2(xr[4], xr[5]), add2(xr[6], xr[7]));                \
        float2 v = up2(add2(s0, s1));                                         \
        XS(buf, 2 * ijp, bb * 4 + (u)) = v.x;                                 \
        XS(buf, 2 * ijp + 1, bb * 4 + (u)) = v.y;                             \
    } while (0)

#define LDG_W(ph)                                                             \
    do {                                                                      \
        const float4* wp = (const float4*)(g_veff +                          \
            (((size_t)sg * 32 + PH_T(ph)) * 64 + ((ph) & 1) * 32) * 64);      \
        wr0 = wp[tid]; wr1 = wp[tid + 256];                                   \
    } while (0)

#define STS_W(buf)                                                            \
    do {                                                                      \
        float4* wd = (float4*)WSBASE(buf);                                    \
        wd[tid] = wr0; wd[tid + 256] = wr1;                                   \
    } while (0)

#define COMP8(buf, k0)                                                        \
    do {                                                                      \
        _Pragma("unroll") for (int k = (k0); k < (k0) + 8; ++k) {             \
            ulonglong2 xp = *(const ulonglong2*)&XS(buf, k, 4 * ty);          \
            float4 wv = *(const float4*)(WSBASE(buf) + k * 64 + 4 * tx);      \
            u64 w0 = pk2(wv.x, wv.x), w1 = pk2(wv.y, wv.y);                   \
            u64 w2 = pk2(wv.z, wv.z), w3 = pk2(wv.w, wv.w);                   \
            fma2(acc[0][0], xp.x, w0); fma2(acc[1][0], xp.y, w0);             \
            fma2(acc[0][1], xp.x, w1); fma2(acc[1][1], xp.y, w1);             \
            fma2(acc[0][2], xp.x, w2); fma2(acc[1][2], xp.y, w2);             \
            fma2(acc[0][3], xp.x, w3); fma2(acc[1][3], xp.y, w3);             \
        }                                                                     \
    } while (0)

    // phase-0 x prefetch + c-reduce into xs[0] BEFORE the spin (hides DRAM
    // latency under the device barrier). xs[0] aliases prep smem — dead above.
    LDG_U(0, 0); STS_U(0, 0);
    LDG_U(0, 1); STS_U(0, 1);
    LDG_U(0, 2); STS_U(0, 2);
    LDG_U(0, 3); STS_U(0, 3);

    // device-wide barrier: wait for all 512 CTAs' veff slices
    if (tid == 0) {
        int v;
        do {
            asm volatile("ld.global.acquire.gpu.b32 %0, [%1];"
                         : "=r"(v) : "l"(&g_prep_ctr) : "memory");
            if (v < GRID) __nanosleep(64);
        } while (v < GRID);
    }
    __syncthreads();

    LDG_W(0);
    STS_W(0);
    __syncthreads();

#pragma unroll
    for (int ph = 0; ph < 4; ++ph) {
        const int buf = ph & 1, nb = buf ^ 1;
        if (ph < 3) {
            LDG_W(ph + 1);
            LDG_U(ph + 1, 0); COMP8(buf, 0);  STS_U(nb, 0);
            LDG_U(ph + 1, 1); COMP8(buf, 8);  STS_U(nb, 1);
            LDG_U(ph + 1, 2); COMP8(buf, 16); STS_U(nb, 2);
            LDG_U(ph + 1, 3); COMP8(buf, 24); STS_U(nb, 3);
            STS_W(nb);
        } else {
            COMP8(buf, 0); COMP8(buf, 8); COMP8(buf, 16); COMP8(buf, 24);
        }
        __syncthreads();
    }

    // write partials: g_part[ks][b][s*64+o]
    {
        const int b0 = mt * 64 + 4 * ty;
        const int obase = sg * 64 + 4 * tx;
#pragma unroll
        for (int p = 0; p < 2; ++p) {
            float2 c0 = up2(acc[p][0]), c1 = up2(acc[p][1]);
            float2 c2 = up2(acc[p][2]), c3 = up2(acc[p][3]);
            float4 r0 = make_float4(c0.x, c1.x, c2.x, c3.x);
            float4 r1 = make_float4(c0.y, c1.y, c2.y, c3.y);
            *(float4*)(g_part + ((size_t)ks << 17) + (size_t)(b0 + 2 * p) * 128 + obase) = r0;
            *(float4*)(g_part + ((size_t)ks << 17) + (size_t)(b0 + 2 * p + 1) * 128 + obase) = r1;
        }
    }

    // ======================= phase C: fused epilogue =======================
    __threadfence();
    __syncthreads();
    if (tid == 0) {
        int old = atomicAdd(&g_grp[bx >> 4], 1);
        s_win = (old == 15);
        if (old == 15) g_grp[bx >> 4] = 0;  // self-reset for next launch
    }
    __syncthreads();

    if (s_win) {
        __threadfence();  // acquire side of the g_grp release chain
        // reduce group (sg, mt): b in [mt*64, mt*64+64), o-cols [sg*64, sg*64+64)
#pragma unroll
        for (int u = 0; u < 4; ++u) {
            int v = tid + 256 * u;          // float4 index within the group block
            int bl = v >> 4, so4 = v & 15;  // b_local, float4-col
            size_t off = (size_t)(mt * 64 + bl) * 128 + sg * 64 + so4 * 4;
            float4 bv = *(const float4*)(bias + sg * 64 + so4 * 4);
            u64 a0 = pk2(bv.x, bv.y), a1 = pk2(bv.z, bv.w);
#pragma unroll
            for (int k = 0; k < KSPLIT; ++k) {
                ulonglong2 pp = *(const ulonglong2*)(g_part + ((size_t)k << 17) + off);
                a0 = add2(a0, pp.x);
                a1 = add2(a1, pp.y);
            }
            float2 f0 = up2(a0), f1 = up2(a1);
            float4 r;
            r.x = (f0.x >= 0.0f) ? f0.x : 0.02f * f0.x;
            r.y = (f0.y >= 0.0f) ? f0.y : 0.02f * f0.y;
            r.z = (f1.x >= 0.0f) ? f1.x : 0.02f * f1.x;
            r.w = (f1.y >= 0.0f) ? f1.y : 0.02f * f1.y;
            *(float4*)(out + off) = r;
        }
        if (tid == 0) {
            int d = atomicAdd(&g_done, 1);
            if (d == 31) {  // last reducer: reset launch-global counters
                g_done = 0;
                g_prep_ctr = 0;
            }
        }
    }
}

// ---------------------------------------------------------------------------
extern "C" void kernel_launch(void* const* d_in, const int* in_sizes, int n_in,
                              void* d_out, int out_size) {
    const float* x = nullptr;
    const float* W = nullptr;
    const float* bias = nullptr;
    for (int i = 0; i < n_in; ++i) {
        if (in_sizes[i] == 1024 * 512 * 64) x = (const float*)d_in[i];
        else if (in_sizes[i] == NSW * NF * 32 * 64) W = (const float*)d_in[i];
        else if (in_sizes[i] == NSW * NF) bias = (const float*)d_in[i];
    }
    if (!x) x = (const float*)d_in[0];
    if (!W) W = (const float*)d_in[1];
    if (!bias) bias = (const float*)d_in[2];

    fused_kernel<<<GRID, 256>>>(x, W, bias, (float*)d_out);
}